// round 14
// baseline (speedup 1.0000x reference)
#include <cuda_runtime.h>
#include <cuda_fp16.h>
#include <stdint.h>

// LSTM, B=4096, T=2048, I=1, H=10.
// Round 14: R13 + fully packed fp16 tail:
//   c  = fmaf(fv, c, ig)            (fp32 accumulator, unchanged)
//   cc2 = {c,c} f16x2; tc2 = tanh2(cc2)
//   to2 = PRMT(tgo, dup-hi)         (ALU pipe)
//   hd  = hfma2(to2, tc2, tc2)      -> already-duplicated {h', h'}
// removing the fp32 tanh, the hown FMA and the final pack from the loop.
// Everything else as R13: fp16 gate-pair matvec (20+2 HFMA2), no syncwarp
// (convergent warp, in-order LSU), pipelined seeds, 3 batches/warp,
// 1366 warps, 3-phase stagger.

#define FULL_MASK 0xFFFFFFFFu

constexpr int Bv = 4096;
constexpr int Tv = 2048;
constexpr int Hv = 10;
constexpr int BATCH_PER_WARP = 3;
constexpr int WARPS_PER_BLOCK = 10;
constexpr int NBLOCKS = 148;                   // 1480 warps launched, 1366 live
constexpr int THREADS = WARPS_PER_BLOCK * 32;  // 320

__device__ __forceinline__ uint32_t smem_u32(const void* p) {
    uint32_t a;
    asm("{ .reg .u64 t; cvta.to.shared.u64 t, %1; cvt.u32.u64 %0, t; }"
        : "=r"(a) : "l"(p));
    return a;
}
__device__ __forceinline__ uint32_t pack_h2(float lo, float hi) {
    uint32_t d;
    asm("cvt.rn.f16x2.f32 %0, %1, %2;" : "=r"(d) : "f"(hi), "f"(lo));
    return d;
}
__device__ __forceinline__ float cvt_lo(uint32_t v) {
    float f;
    asm("{ .reg .b16 l, h; mov.b32 {l, h}, %1; cvt.f32.f16 %0, l; }"
        : "=f"(f) : "r"(v));
    return f;
}
__device__ __forceinline__ float cvt_hi(uint32_t v) {
    float f;
    asm("{ .reg .b16 l, h; mov.b32 {l, h}, %1; cvt.f32.f16 %0, h; }"
        : "=f"(f) : "r"(v));
    return f;
}
__device__ __forceinline__ uint32_t hfma2(uint32_t a, uint32_t b, uint32_t c) {
    uint32_t d;
    asm("fma.rn.f16x2 %0, %1, %2, %3;" : "=r"(d) : "r"(a), "r"(b), "r"(c));
    return d;
}
__device__ __forceinline__ uint32_t hmul2(uint32_t a, uint32_t b) {
    uint32_t d;
    asm("mul.rn.f16x2 %0, %1, %2;" : "=r"(d) : "r"(a), "r"(b));
    return d;
}
__device__ __forceinline__ uint32_t tanh2_h(uint32_t a) {
    uint32_t d;
    asm("tanh.approx.f16x2 %0, %1;" : "=r"(d) : "r"(a));
    return d;
}
// Duplicate the high 16-bit half across both halves: bytes {2,3,2,3}.
__device__ __forceinline__ uint32_t dup_hi16(uint32_t v) {
    uint32_t d;
    asm("prmt.b32 %0, %1, %1, 0x3232;" : "=r"(d) : "r"(v));
    return d;
}

// Ordered smem ops (compiler barriers; HW order via per-warp in-order LSU
// for a convergent warp — validated correct in R13).
__device__ __forceinline__ void sts32(uint32_t addr, uint32_t v) {
    asm volatile("st.shared.b32 [%0], %1;" :: "r"(addr), "r"(v) : "memory");
}
__device__ __forceinline__ void lds128(uint32_t addr, uint32_t& a, uint32_t& b,
                                       uint32_t& c, uint32_t& d) {
    asm volatile("ld.shared.v4.b32 {%0, %1, %2, %3}, [%4];"
                 : "=r"(a), "=r"(b), "=r"(c), "=r"(d) : "r"(addr) : "memory");
}
__device__ __forceinline__ void lds64(uint32_t addr, uint32_t& a, uint32_t& b) {
    asm volatile("ld.shared.v2.b32 {%0, %1}, [%2];"
                 : "=r"(a), "=r"(b) : "r"(addr) : "memory");
}

__global__ void __launch_bounds__(THREADS, 1)
lstm_kernel(const float* __restrict__ x,
            const float* __restrict__ W_ih,   // [40,1]
            const float* __restrict__ W_hh,   // [40,10]
            const float* __restrict__ b_ih,   // [40]
            const float* __restrict__ b_hh,   // [40]
            const float* __restrict__ W_out,  // [1,10]
            const float* __restrict__ b_out,  // [1]
            float* __restrict__ out)          // [4096]
{
    // h exchange, duplicated f16x2: hbuf[..][j] = {h'[j], h'[j]}.
    __shared__ __align__(16) uint32_t hbuf[2][WARPS_PER_BLOCK][4][12];

    const int warp = threadIdx.x >> 5;
    const int lane = threadIdx.x & 31;
    const int gw   = blockIdx.x * WARPS_PER_BLOCK + warp;
    if (gw * BATCH_PER_WARP >= Bv) return;     // whole-warp exit

    const int g    = lane / 10;                // 0..2 batches, 3 = idle lanes
    const int j    = lane - g * 10;            // hidden unit owned by this lane
    const int base = g * 10;
    const int batch = gw * BATCH_PER_WARP + g;
    const bool active = (g < 3) && (batch < Bv);
    const int b = active ? batch : 0;          // clamp for safe loads

    // ---- Weights. Gate scales: i,f,o = 0.5 (sigmoid fold), g = 1.0.
    // h stored as h'=2h -> W_hh rows get an extra 0.5. All matvec data f16x2.
    uint32_t wih16_if, wih16_go, bias16_if, bias16_go;
    uint32_t wif16[10], wgo16[10];
    {
        const int ri = 0 * 10 + j, rf = 1 * 10 + j, rg = 2 * 10 + j, ro = 3 * 10 + j;
        bias16_if = pack_h2((b_ih[ri] + b_hh[ri]) * 0.5f, (b_ih[rf] + b_hh[rf]) * 0.5f);
        bias16_go = pack_h2((b_ih[rg] + b_hh[rg]) * 1.0f, (b_ih[ro] + b_hh[ro]) * 0.5f);
        wih16_if  = pack_h2(W_ih[ri] * 0.5f, W_ih[rf] * 0.5f);
        wih16_go  = pack_h2(W_ih[rg] * 1.0f, W_ih[ro] * 0.5f);
#pragma unroll
        for (int k = 0; k < 10; k++) {
            wif16[k] = pack_h2(W_hh[ri * Hv + k] * 0.25f, W_hh[rf * Hv + k] * 0.25f);
            wgo16[k] = pack_h2(W_hh[rg * Hv + k] * 0.5f,  W_hh[ro * Hv + k] * 0.25f);
        }
    }
    const uint32_t half2_16 = pack_h2(0.5f, 0.5f);

    // ---- State: duplicated f16x2 h', fp32 c.
    uint32_t h2d[10];
#pragma unroll
    for (int k = 0; k < 10; k++) h2d[k] = 0u;
    float c = 0.f;
    uint32_t hd = 0u;                          // {h', h'} f16x2 of own unit

    uint32_t st_addr[2], ld_addr[2];
    {
        const uint32_t b0 = smem_u32(&hbuf[0][warp][g][0]);
        const uint32_t b1 = smem_u32(&hbuf[1][warp][g][0]);
        st_addr[0] = b0 + 4u * (uint32_t)j;
        st_addr[1] = b1 + 4u * (uint32_t)j;
        ld_addr[0] = b0;
        ld_addr[1] = b1;
    }

    const float4* x4 = reinterpret_cast<const float4*>(x + (size_t)b * Tv);
    float4 nx = x4[0];                         // double-buffered x (4 steps/load)

    // ---- 3-phase stagger: warps {s, s+4, s+8} share an SMSP; delay by
    // (warp>>2) * ~1/3 step via a dependent FMA chain.
    {
        const int reps = (warp >> 2) * 20;     // 0 / 20 / 40 dependent FFMA
        float d = 1.0f + (float)lane;
        for (int it = 0; it < reps; it++) d = fmaf(d, 1.0000001f, 1.0f);
        if (d == -1.0f) out[0] = d;            // never true; keeps the chain
    }

    // ---- Pipelined seeds for step 0.
    uint32_t aif, ago;
    {
        const uint32_t xh2 = pack_h2(nx.x, nx.x);
        aif = hfma2(xh2, wih16_if, bias16_if);
        ago = hfma2(xh2, wih16_go, bias16_go);
    }

    for (int t0 = 0; t0 < Tv; t0 += 4) {
        const float4 cur = nx;
        const int nxt = (t0 >> 2) + 1;
        if (nxt < Tv / 4) nx = x4[nxt];

#pragma unroll
        for (int u = 0; u < 4; u++) {
            // 2 packed 10-deep f16x2 chains (i,f) and (g,o); aif/ago carry the
            // pre-computed seed (x*W_ih + b).
#pragma unroll
            for (int k = 0; k < 10; k++) {
                aif = hfma2(h2d[k], wif16[k], aif);
                ago = hfma2(h2d[k], wgo16[k], ago);
            }

            // Packed activations + packed c-path front end.
            const uint32_t tif = tanh2_h(aif);   // {ti, tf}
            const uint32_t tgo = tanh2_h(ago);   // {tg, to}
            const uint32_t s2  = hfma2(half2_16, tif, half2_16); // {i, f}
            const uint32_t m2  = hmul2(s2, tgo);                 // {i*g, junk}

            const float ig = cvt_lo(m2);
            const float fv = cvt_hi(s2);

            // fp32 c accumulator, then fp16 packed tail:
            // tc2 = tanh2({c,c}); hd = to2*tc2 + tc2 = {h', h'} directly.
            c = fmaf(fv, c, ig);
            const uint32_t cc2 = pack_h2(c, c);
            const uint32_t tc2 = tanh2_h(cc2);
            const uint32_t to2 = dup_hi16(tgo);  // {to, to} (ALU pipe)
            hd = hfma2(to2, tc2, tc2);           // h' = 2h, duplicated

            // Exchange (no syncwarp: convergent warp, in-order per-warp LSU).
            const int par = u & 1;
            sts32(st_addr[par], hd);

            // Seeds for the NEXT step fill the store->load window.
            {
                const float xt_n = (u == 0) ? cur.y : (u == 1) ? cur.z
                                 : (u == 2) ? cur.w : nx.x;
                const uint32_t xh2 = pack_h2(xt_n, xt_n);
                aif = hfma2(xh2, wih16_if, bias16_if);
                ago = hfma2(xh2, wih16_go, bias16_go);
            }

            lds128(ld_addr[par],      h2d[0], h2d[1], h2d[2], h2d[3]);
            lds128(ld_addr[par] + 16, h2d[4], h2d[5], h2d[6], h2d[7]);
            lds64 (ld_addr[par] + 32, h2d[8], h2d[9]);
        }
    }

    // ---- Epilogue: out[b] = h . W_out + b_out, with h = 0.5*h'.
    const float hown = cvt_lo(hd);             // fp16-rounded h' (same as exchanged)
    const float p = hown * (W_out[j] * 0.5f);
    float sum = 0.f;
#pragma unroll
    for (int k = 0; k < 10; k++) {
        sum += __shfl_sync(FULL_MASK, p, base + k);
    }
    if (active && j == 0) {
        out[b] = sum + b_out[0];
    }
}

extern "C" void kernel_launch(void* const* d_in, const int* in_sizes, int n_in,
                              void* d_out, int out_size) {
    (void)in_sizes; (void)n_in; (void)out_size;
    const float* x     = (const float*)d_in[0];
    const float* W_ih  = (const float*)d_in[1];
    const float* W_hh  = (const float*)d_in[2];
    const float* b_ih  = (const float*)d_in[3];
    const float* b_hh  = (const float*)d_in[4];
    const float* W_out = (const float*)d_in[5];
    const float* b_out = (const float*)d_in[6];
    float* out = (float*)d_out;

    lstm_kernel<<<NBLOCKS, THREADS>>>(x, W_ih, W_hh, b_ih, b_hh, W_out, b_out, out);
}

// round 15
// speedup vs baseline: 1.0633x; 1.0633x over previous
#include <cuda_runtime.h>
#include <cuda_fp16.h>
#include <stdint.h>

// LSTM, B=4096, T=2048, I=1, H=10.
// Round 15: R13 (best: 245.9us) with the R14 tail REVERTED (scalar fp32 tail
// was faster), plus split fp16 matvec: each gate-pair chain becomes two
// independent 5-deep halves joined by HADD2 (dep depth 40 -> 24 cyc, 4
// independent chains for scheduler slack on the 3-warp hot SMSPs).
// Core design: fp16 gate-pair matvec, fp32 c-path, 3 batches/warp, 1366
// warps, smem h-exchange without syncwarp, pipelined seeds, 3-phase stagger.

#define FULL_MASK 0xFFFFFFFFu

constexpr int Bv = 4096;
constexpr int Tv = 2048;
constexpr int Hv = 10;
constexpr int BATCH_PER_WARP = 3;
constexpr int WARPS_PER_BLOCK = 10;
constexpr int NBLOCKS = 148;                   // 1480 warps launched, 1366 live
constexpr int THREADS = WARPS_PER_BLOCK * 32;  // 320

__device__ __forceinline__ uint32_t smem_u32(const void* p) {
    uint32_t a;
    asm("{ .reg .u64 t; cvta.to.shared.u64 t, %1; cvt.u32.u64 %0, t; }"
        : "=r"(a) : "l"(p));
    return a;
}
__device__ __forceinline__ uint32_t pack_h2(float lo, float hi) {
    uint32_t d;
    asm("cvt.rn.f16x2.f32 %0, %1, %2;" : "=r"(d) : "f"(hi), "f"(lo));
    return d;
}
__device__ __forceinline__ float cvt_lo(uint32_t v) {
    float f;
    asm("{ .reg .b16 l, h; mov.b32 {l, h}, %1; cvt.f32.f16 %0, l; }"
        : "=f"(f) : "r"(v));
    return f;
}
__device__ __forceinline__ float cvt_hi(uint32_t v) {
    float f;
    asm("{ .reg .b16 l, h; mov.b32 {l, h}, %1; cvt.f32.f16 %0, h; }"
        : "=f"(f) : "r"(v));
    return f;
}
__device__ __forceinline__ uint32_t hfma2(uint32_t a, uint32_t b, uint32_t c) {
    uint32_t d;
    asm("fma.rn.f16x2 %0, %1, %2, %3;" : "=r"(d) : "r"(a), "r"(b), "r"(c));
    return d;
}
__device__ __forceinline__ uint32_t hmul2(uint32_t a, uint32_t b) {
    uint32_t d;
    asm("mul.rn.f16x2 %0, %1, %2;" : "=r"(d) : "r"(a), "r"(b));
    return d;
}
__device__ __forceinline__ uint32_t hadd2(uint32_t a, uint32_t b) {
    uint32_t d;
    asm("add.rn.f16x2 %0, %1, %2;" : "=r"(d) : "r"(a), "r"(b));
    return d;
}
__device__ __forceinline__ uint32_t tanh2_h(uint32_t a) {
    uint32_t d;
    asm("tanh.approx.f16x2 %0, %1;" : "=r"(d) : "r"(a));
    return d;
}
__device__ __forceinline__ float tanh_a(float x) {
    float r; asm("tanh.approx.f32 %0, %1;" : "=f"(r) : "f"(x)); return r;
}

// Ordered smem ops (compiler barriers; HW order via per-warp in-order LSU
// for a convergent warp — validated correct in R13/R14).
__device__ __forceinline__ void sts32(uint32_t addr, uint32_t v) {
    asm volatile("st.shared.b32 [%0], %1;" :: "r"(addr), "r"(v) : "memory");
}
__device__ __forceinline__ void lds128(uint32_t addr, uint32_t& a, uint32_t& b,
                                       uint32_t& c, uint32_t& d) {
    asm volatile("ld.shared.v4.b32 {%0, %1, %2, %3}, [%4];"
                 : "=r"(a), "=r"(b), "=r"(c), "=r"(d) : "r"(addr) : "memory");
}
__device__ __forceinline__ void lds64(uint32_t addr, uint32_t& a, uint32_t& b) {
    asm volatile("ld.shared.v2.b32 {%0, %1}, [%2];"
                 : "=r"(a), "=r"(b) : "r"(addr) : "memory");
}

__global__ void __launch_bounds__(THREADS, 1)
lstm_kernel(const float* __restrict__ x,
            const float* __restrict__ W_ih,   // [40,1]
            const float* __restrict__ W_hh,   // [40,10]
            const float* __restrict__ b_ih,   // [40]
            const float* __restrict__ b_hh,   // [40]
            const float* __restrict__ W_out,  // [1,10]
            const float* __restrict__ b_out,  // [1]
            float* __restrict__ out)          // [4096]
{
    // h exchange, duplicated f16x2: hbuf[..][j] = {h'[j], h'[j]}.
    __shared__ __align__(16) uint32_t hbuf[2][WARPS_PER_BLOCK][4][12];

    const int warp = threadIdx.x >> 5;
    const int lane = threadIdx.x & 31;
    const int gw   = blockIdx.x * WARPS_PER_BLOCK + warp;
    if (gw * BATCH_PER_WARP >= Bv) return;     // whole-warp exit

    const int g    = lane / 10;                // 0..2 batches, 3 = idle lanes
    const int j    = lane - g * 10;            // hidden unit owned by this lane
    const int base = g * 10;
    const int batch = gw * BATCH_PER_WARP + g;
    const bool active = (g < 3) && (batch < Bv);
    const int b = active ? batch : 0;          // clamp for safe loads

    // ---- Weights. Gate scales: i,f,o = 0.5 (sigmoid fold), g = 1.0.
    // h stored as h'=2h -> W_hh rows get an extra 0.5. All matvec data f16x2.
    uint32_t wih16_if, wih16_go, bias16_if, bias16_go;
    uint32_t wif16[10], wgo16[10];
    {
        const int ri = 0 * 10 + j, rf = 1 * 10 + j, rg = 2 * 10 + j, ro = 3 * 10 + j;
        bias16_if = pack_h2((b_ih[ri] + b_hh[ri]) * 0.5f, (b_ih[rf] + b_hh[rf]) * 0.5f);
        bias16_go = pack_h2((b_ih[rg] + b_hh[rg]) * 1.0f, (b_ih[ro] + b_hh[ro]) * 0.5f);
        wih16_if  = pack_h2(W_ih[ri] * 0.5f, W_ih[rf] * 0.5f);
        wih16_go  = pack_h2(W_ih[rg] * 1.0f, W_ih[ro] * 0.5f);
#pragma unroll
        for (int k = 0; k < 10; k++) {
            wif16[k] = pack_h2(W_hh[ri * Hv + k] * 0.25f, W_hh[rf * Hv + k] * 0.25f);
            wgo16[k] = pack_h2(W_hh[rg * Hv + k] * 0.5f,  W_hh[ro * Hv + k] * 0.25f);
        }
    }
    const uint32_t half2_16 = pack_h2(0.5f, 0.5f);

    // ---- State: duplicated f16x2 h', fp32 c.
    uint32_t h2d[10];
#pragma unroll
    for (int k = 0; k < 10; k++) h2d[k] = 0u;
    float c = 0.f, hown = 0.f;                 // hown = h' (fp32 master copy)

    uint32_t st_addr[2], ld_addr[2];
    {
        const uint32_t b0 = smem_u32(&hbuf[0][warp][g][0]);
        const uint32_t b1 = smem_u32(&hbuf[1][warp][g][0]);
        st_addr[0] = b0 + 4u * (uint32_t)j;
        st_addr[1] = b1 + 4u * (uint32_t)j;
        ld_addr[0] = b0;
        ld_addr[1] = b1;
    }

    const float4* x4 = reinterpret_cast<const float4*>(x + (size_t)b * Tv);
    float4 nx = x4[0];                         // double-buffered x (4 steps/load)

    // ---- 3-phase stagger: warps {s, s+4, s+8} share an SMSP; delay by
    // (warp>>2) * ~1/3 step via a dependent FMA chain.
    {
        const int reps = (warp >> 2) * 20;     // 0 / 20 / 40 dependent FFMA
        float d = 1.0f + (float)lane;
        for (int it = 0; it < reps; it++) d = fmaf(d, 1.0000001f, 1.0f);
        if (d == -1.0f) out[0] = d;            // never true; keeps the chain
    }

    // ---- Pipelined seeds for step 0 (front halves carry x*W_ih + b).
    uint32_t aif, ago;
    {
        const uint32_t xh2 = pack_h2(nx.x, nx.x);
        aif = hfma2(xh2, wih16_if, bias16_if);
        ago = hfma2(xh2, wih16_go, bias16_go);
    }

    for (int t0 = 0; t0 < Tv; t0 += 4) {
        const float4 cur = nx;
        const int nxt = (t0 >> 2) + 1;
        if (nxt < Tv / 4) nx = x4[nxt];

#pragma unroll
        for (int u = 0; u < 4; u++) {
            // Split matvec: 4 independent chains of depth <=5.
            // Front halves (aif/ago) carry the pipelined seed; back halves
            // (aifB/agoB) start from a product.
            uint32_t aifB = hmul2(h2d[5], wif16[5]);
            uint32_t agoB = hmul2(h2d[5], wgo16[5]);
#pragma unroll
            for (int k = 0; k < 5; k++) {
                aif = hfma2(h2d[k], wif16[k], aif);
                ago = hfma2(h2d[k], wgo16[k], ago);
                if (k < 4) {
                    aifB = hfma2(h2d[6 + k], wif16[6 + k], aifB);
                    agoB = hfma2(h2d[6 + k], wgo16[6 + k], agoB);
                }
            }
            aif = hadd2(aif, aifB);
            ago = hadd2(ago, agoB);

            // Packed activations + packed c-path front end.
            const uint32_t tif = tanh2_h(aif);   // {ti, tf}
            const uint32_t tgo = tanh2_h(ago);   // {tg, to}
            const uint32_t s2  = hfma2(half2_16, tif, half2_16); // {i, f}
            const uint32_t m2  = hmul2(s2, tgo);                 // {i*g, junk}

            const float ig = cvt_lo(m2);
            const float fv = cvt_hi(s2);
            const float to = cvt_hi(tgo);

            // fp32 tail (R13 form — fastest measured).
            c = fmaf(fv, c, ig);
            const float tc = tanh_a(c);
            hown = fmaf(to, tc, tc);             // h' = 2h

            // Exchange (no syncwarp: convergent warp, in-order per-warp LSU).
            const int par = u & 1;
            const uint32_t hd = pack_h2(hown, hown);
            sts32(st_addr[par], hd);

            // Seeds for the NEXT step fill the store->load window.
            {
                const float xt_n = (u == 0) ? cur.y : (u == 1) ? cur.z
                                 : (u == 2) ? cur.w : nx.x;
                const uint32_t xh2 = pack_h2(xt_n, xt_n);
                aif = hfma2(xh2, wih16_if, bias16_if);
                ago = hfma2(xh2, wih16_go, bias16_go);
            }

            lds128(ld_addr[par],      h2d[0], h2d[1], h2d[2], h2d[3]);
            lds128(ld_addr[par] + 16, h2d[4], h2d[5], h2d[6], h2d[7]);
            lds64 (ld_addr[par] + 32, h2d[8], h2d[9]);
        }
    }

    // ---- Epilogue: out[b] = h . W_out + b_out, with h = 0.5*h'.
    const float p = hown * (W_out[j] * 0.5f);
    float sum = 0.f;
#pragma unroll
    for (int k = 0; k < 10; k++) {
        sum += __shfl_sync(FULL_MASK, p, base + k);
    }
    if (active && j == 0) {
        out[b] = sum + b_out[0];
    }
}

extern "C" void kernel_launch(void* const* d_in, const int* in_sizes, int n_in,
                              void* d_out, int out_size) {
    (void)in_sizes; (void)n_in; (void)out_size;
    const float* x     = (const float*)d_in[0];
    const float* W_ih  = (const float*)d_in[1];
    const float* W_hh  = (const float*)d_in[2];
    const float* b_ih  = (const float*)d_in[3];
    const float* b_hh  = (const float*)d_in[4];
    const float* W_out = (const float*)d_in[5];
    const float* b_out = (const float*)d_in[6];
    float* out = (float*)d_out;

    lstm_kernel<<<NBLOCKS, THREADS>>>(x, W_ih, W_hh, b_ih, b_hh, W_out, b_out, out);
}

// round 17
// speedup vs baseline: 1.1196x; 1.0530x over previous
#include <cuda_runtime.h>
#include <cuda_fp16.h>
#include <stdint.h>

// LSTM, B=4096, T=2048, I=1, H=10.
// FINAL (= Round 13, the measured optimum at 245.9us; R14/R15 variants both
// regressed; R16 was an infra failure — resubmitted unchanged). Design:
//  - lane = (batch, unit): 3 single batches per warp (10 lanes each),
//    1366 live warps across 148 blocks x 10 warps.
//  - recurrent matvec in packed fp16: gate pairs (i,f),(g,o) share one
//    11-deep fma.rn.f16x2 chain each (20 HFMA2 + 2 pipelined seed HFMA2).
//  - activations: tanh.approx.f16x2 on the gate pairs; sigmoid folded as
//    0.5*tanh(a/2)+0.5 into pre-scaled weights; h stored as h'=2h.
//  - c accumulator and the c->tanh->h tail in fp32 (precision-critical).
//  - h broadcast via smem (STS.32 + 2xLDS.128 + LDS.64, parity
//    double-buffered), NO syncwarp: warp is convergent, per-warp LSU is
//    in-order; compiler ordering via asm volatile + memory clobbers.
//  - next step's x-seeds computed inside the STS->LDS window.
//  - 3-phase stagger de-phases the 3 warps sharing each hot SMSP.

#define FULL_MASK 0xFFFFFFFFu

constexpr int Bv = 4096;
constexpr int Tv = 2048;
constexpr int Hv = 10;
constexpr int BATCH_PER_WARP = 3;
constexpr int WARPS_PER_BLOCK = 10;
constexpr int NBLOCKS = 148;                   // 1480 warps launched, 1366 live
constexpr int THREADS = WARPS_PER_BLOCK * 32;  // 320

__device__ __forceinline__ uint32_t smem_u32(const void* p) {
    uint32_t a;
    asm("{ .reg .u64 t; cvta.to.shared.u64 t, %1; cvt.u32.u64 %0, t; }"
        : "=r"(a) : "l"(p));
    return a;
}
__device__ __forceinline__ uint32_t pack_h2(float lo, float hi) {
    uint32_t d;
    asm("cvt.rn.f16x2.f32 %0, %1, %2;" : "=r"(d) : "f"(hi), "f"(lo));
    return d;
}
__device__ __forceinline__ float cvt_lo(uint32_t v) {
    float f;
    asm("{ .reg .b16 l, h; mov.b32 {l, h}, %1; cvt.f32.f16 %0, l; }"
        : "=f"(f) : "r"(v));
    return f;
}
__device__ __forceinline__ float cvt_hi(uint32_t v) {
    float f;
    asm("{ .reg .b16 l, h; mov.b32 {l, h}, %1; cvt.f32.f16 %0, h; }"
        : "=f"(f) : "r"(v));
    return f;
}
__device__ __forceinline__ uint32_t hfma2(uint32_t a, uint32_t b, uint32_t c) {
    uint32_t d;
    asm("fma.rn.f16x2 %0, %1, %2, %3;" : "=r"(d) : "r"(a), "r"(b), "r"(c));
    return d;
}
__device__ __forceinline__ uint32_t hmul2(uint32_t a, uint32_t b) {
    uint32_t d;
    asm("mul.rn.f16x2 %0, %1, %2;" : "=r"(d) : "r"(a), "r"(b));
    return d;
}
__device__ __forceinline__ uint32_t tanh2_h(uint32_t a) {
    uint32_t d;
    asm("tanh.approx.f16x2 %0, %1;" : "=r"(d) : "r"(a));
    return d;
}
__device__ __forceinline__ float tanh_a(float x) {
    float r; asm("tanh.approx.f32 %0, %1;" : "=f"(r) : "f"(x)); return r;
}

// Ordered smem ops (compiler barriers; HW order via per-warp in-order LSU
// for a convergent warp — validated correct in R13/R14/R15).
__device__ __forceinline__ void sts32(uint32_t addr, uint32_t v) {
    asm volatile("st.shared.b32 [%0], %1;" :: "r"(addr), "r"(v) : "memory");
}
__device__ __forceinline__ void lds128(uint32_t addr, uint32_t& a, uint32_t& b,
                                       uint32_t& c, uint32_t& d) {
    asm volatile("ld.shared.v4.b32 {%0, %1, %2, %3}, [%4];"
                 : "=r"(a), "=r"(b), "=r"(c), "=r"(d) : "r"(addr) : "memory");
}
__device__ __forceinline__ void lds64(uint32_t addr, uint32_t& a, uint32_t& b) {
    asm volatile("ld.shared.v2.b32 {%0, %1}, [%2];"
                 : "=r"(a), "=r"(b) : "r"(addr) : "memory");
}

__global__ void __launch_bounds__(THREADS, 1)
lstm_kernel(const float* __restrict__ x,
            const float* __restrict__ W_ih,   // [40,1]
            const float* __restrict__ W_hh,   // [40,10]
            const float* __restrict__ b_ih,   // [40]
            const float* __restrict__ b_hh,   // [40]
            const float* __restrict__ W_out,  // [1,10]
            const float* __restrict__ b_out,  // [1]
            float* __restrict__ out)          // [4096]
{
    // h exchange, duplicated f16x2: hbuf[..][j] = {h'[j], h'[j]}.
    __shared__ __align__(16) uint32_t hbuf[2][WARPS_PER_BLOCK][4][12];

    const int warp = threadIdx.x >> 5;
    const int lane = threadIdx.x & 31;
    const int gw   = blockIdx.x * WARPS_PER_BLOCK + warp;
    if (gw * BATCH_PER_WARP >= Bv) return;     // whole-warp exit

    const int g    = lane / 10;                // 0..2 batches, 3 = idle lanes
    const int j    = lane - g * 10;            // hidden unit owned by this lane
    const int base = g * 10;
    const int batch = gw * BATCH_PER_WARP + g;
    const bool active = (g < 3) && (batch < Bv);
    const int b = active ? batch : 0;          // clamp for safe loads

    // ---- Weights. Gate scales: i,f,o = 0.5 (sigmoid fold), g = 1.0.
    // h stored as h'=2h -> W_hh rows get an extra 0.5. All matvec data f16x2.
    uint32_t wih16_if, wih16_go, bias16_if, bias16_go;
    uint32_t wif16[10], wgo16[10];
    {
        const int ri = 0 * 10 + j, rf = 1 * 10 + j, rg = 2 * 10 + j, ro = 3 * 10 + j;
        bias16_if = pack_h2((b_ih[ri] + b_hh[ri]) * 0.5f, (b_ih[rf] + b_hh[rf]) * 0.5f);
        bias16_go = pack_h2((b_ih[rg] + b_hh[rg]) * 1.0f, (b_ih[ro] + b_hh[ro]) * 0.5f);
        wih16_if  = pack_h2(W_ih[ri] * 0.5f, W_ih[rf] * 0.5f);
        wih16_go  = pack_h2(W_ih[rg] * 1.0f, W_ih[ro] * 0.5f);
#pragma unroll
        for (int k = 0; k < 10; k++) {
            wif16[k] = pack_h2(W_hh[ri * Hv + k] * 0.25f, W_hh[rf * Hv + k] * 0.25f);
            wgo16[k] = pack_h2(W_hh[rg * Hv + k] * 0.5f,  W_hh[ro * Hv + k] * 0.25f);
        }
    }
    const uint32_t half2_16 = pack_h2(0.5f, 0.5f);

    // ---- State: duplicated f16x2 h', fp32 c.
    uint32_t h2d[10];
#pragma unroll
    for (int k = 0; k < 10; k++) h2d[k] = 0u;
    float c = 0.f, hown = 0.f;                 // hown = h' (fp32 master copy)

    uint32_t st_addr[2], ld_addr[2];
    {
        const uint32_t b0 = smem_u32(&hbuf[0][warp][g][0]);
        const uint32_t b1 = smem_u32(&hbuf[1][warp][g][0]);
        st_addr[0] = b0 + 4u * (uint32_t)j;
        st_addr[1] = b1 + 4u * (uint32_t)j;
        ld_addr[0] = b0;
        ld_addr[1] = b1;
    }

    const float4* x4 = reinterpret_cast<const float4*>(x + (size_t)b * Tv);
    float4 nx = x4[0];                         // double-buffered x (4 steps/load)

    // ---- 3-phase stagger: warps {s, s+4, s+8} share an SMSP; delay by
    // (warp>>2) * ~1/3 step via a dependent FMA chain.
    {
        const int reps = (warp >> 2) * 20;     // 0 / 20 / 40 dependent FFMA
        float d = 1.0f + (float)lane;
        for (int it = 0; it < reps; it++) d = fmaf(d, 1.0000001f, 1.0f);
        if (d == -1.0f) out[0] = d;            // never true; keeps the chain
    }

    // ---- Pipelined seeds for step 0.
    uint32_t aif, ago;
    {
        const uint32_t xh2 = pack_h2(nx.x, nx.x);
        aif = hfma2(xh2, wih16_if, bias16_if);
        ago = hfma2(xh2, wih16_go, bias16_go);
    }

    for (int t0 = 0; t0 < Tv; t0 += 4) {
        const float4 cur = nx;
        const int nxt = (t0 >> 2) + 1;
        if (nxt < Tv / 4) nx = x4[nxt];

#pragma unroll
        for (int u = 0; u < 4; u++) {
            // 2 packed 10-deep f16x2 chains (i,f) and (g,o); aif/ago carry the
            // pre-computed seed (x*W_ih + b).
#pragma unroll
            for (int k = 0; k < 10; k++) {
                aif = hfma2(h2d[k], wif16[k], aif);
                ago = hfma2(h2d[k], wgo16[k], ago);
            }

            // Packed activations + packed c-path front end.
            const uint32_t tif = tanh2_h(aif);   // {ti, tf}
            const uint32_t tgo = tanh2_h(ago);   // {tg, to}
            const uint32_t s2  = hfma2(half2_16, tif, half2_16); // {i, f}
            const uint32_t m2  = hmul2(s2, tgo);                 // {i*g, junk}

            const float ig = cvt_lo(m2);
            const float fv = cvt_hi(s2);
            const float to = cvt_hi(tgo);

            // fp32 tail: c = f*c + i*g, h' = to*tc + tc.
            c = fmaf(fv, c, ig);
            const float tc = tanh_a(c);
            hown = fmaf(to, tc, tc);             // h' = 2h

            // Exchange (no syncwarp: convergent warp, in-order per-warp LSU).
            const int par = u & 1;
            const uint32_t hd = pack_h2(hown, hown);
            sts32(st_addr[par], hd);

            // Seeds for the NEXT step fill the store->load window.
            {
                const float xt_n = (u == 0) ? cur.y : (u == 1) ? cur.z
                                 : (u == 2) ? cur.w : nx.x;
                const uint32_t xh2 = pack_h2(xt_n, xt_n);
                aif = hfma2(xh2, wih16_if, bias16_if);
                ago = hfma2(xh2, wih16_go, bias16_go);
            }

            lds128(ld_addr[par],      h2d[0], h2d[1], h2d[2], h2d[3]);
            lds128(ld_addr[par] + 16, h2d[4], h2d[5], h2d[6], h2d[7]);
            lds64 (ld_addr[par] + 32, h2d[8], h2d[9]);
        }
    }

    // ---- Epilogue: out[b] = h . W_out + b_out, with h = 0.5*h'.
    const float p = hown * (W_out[j] * 0.5f);
    float sum = 0.f;
#pragma unroll
    for (int k = 0; k < 10; k++) {
        sum += __shfl_sync(FULL_MASK, p, base + k);
    }
    if (active && j == 0) {
        out[b] = sum + b_out[0];
    }
}

extern "C" void kernel_launch(void* const* d_in, const int* in_sizes, int n_in,
                              void* d_out, int out_size) {
    (void)in_sizes; (void)n_in; (void)out_size;
    const float* x     = (const float*)d_in[0];
    const float* W_ih  = (const float*)d_in[1];
    const float* W_hh  = (const float*)d_in[2];
    const float* b_ih  = (const float*)d_in[3];
    const float* b_hh  = (const float*)d_in[4];
    const float* W_out = (const float*)d_in[5];
    const float* b_out = (const float*)d_in[6];
    float* out = (float*)d_out;

    lstm_kernel<<<NBLOCKS, THREADS>>>(x, W_ih, W_hh, b_ih, b_hh, W_out, b_out, out);
}